// round 16
// baseline (speedup 1.0000x reference)
#include <cuda_runtime.h>
#include <cuda_bf16.h>
#include <math.h>

#define NMAX 100000
#define EMAX 400000
#define DHD  128
#define DIN  32
#define GR   130   // K-major smem X-tile row stride (even: LDS.64-aligned)
__device__ __constant__ float EPSC = 1e-5f;

// ------------- device scratch (no runtime allocation allowed) ---------------
__device__ float  g_H[(size_t)NMAX * DHD];     // layer-1 GEMM output
__device__ float  g_A[(size_t)NMAX * DHD];     // layer-2 GEMM output
__device__ float  g_dinv[NMAX];
__device__ int    g_cnt[NMAX];
__device__ int    g_fill[NMAX];      // CSR fill cursor, pre-seeded to rowptr[i]
__device__ int    g_rowptr[NMAX + 1];
__device__ int    g_col[EMAX];
__device__ float  g_val[EMAX];
__device__ float  g_y[NMAX];
__device__ float  g_gy[NMAX];
__device__ double g_sum[DHD];
__device__ double g_sq[DHD];
__device__ float  g_scale[DHD];
__device__ float  g_beta[DHD];
__device__ int    g_is32 = 0;   // only ever set to 1 (idempotent across graph replays)

// --------------------------- f32x2 helpers ----------------------------------
__device__ __forceinline__ void unpk2(unsigned long long v, float& lo, float& hi) {
    asm("mov.b64 {%0, %1}, %2;" : "=f"(lo), "=f"(hi) : "l"(v));
}
#define FMA2(c, a, b) asm("fma.rn.f32x2 %0, %1, %2, %0;" : "+l"(c) : "l"(a), "l"(b))

// --------------------------- small helpers ---------------------------------
__device__ __forceinline__ void load_edge(const void* ei, int E, int e, int& s, int& d) {
    if (g_is32) {
        const int* p = (const int*)ei;
        s = p[e]; d = p[E + e];
    } else {
        const long long* p = (const long long*)ei;
        s = (int)p[e]; d = (int)p[E + e];
    }
}
__device__ __forceinline__ int load_dst(const void* ei, int E, int e) {
    if (g_is32) return ((const int*)ei)[E + e];
    return (int)((const long long*)ei)[E + e];
}

// ---------------- preprocessing (merged: zero + detect + stats-zero) --------
__global__ void k_zero_init(const void* ei, int n) {
    int i = blockIdx.x * blockDim.x + threadIdx.x;
    if (i < n) g_cnt[i] = 0;
    if (i < DHD) { g_sum[i] = 0.0; g_sq[i] = 0.0; }
    if (i < 4096) {                     // int32 vs int64 detect (set-only)
        int w = ((const int*)ei)[2 * i + 1];
        if (w != 0) g_is32 = 1;
    }
}

__global__ void k_count(const void* ei, int E) {
    int e = blockIdx.x * blockDim.x + threadIdx.x;
    if (e < E) atomicAdd(&g_cnt[load_dst(ei, E, e)], 1);
}

// Single-block scan: rowptr (exclusive), fill-cursor seed, dinv — one kernel.
__global__ void __launch_bounds__(1024) k_scan_one(int n) {
    __shared__ int sh[1024];
    int t = threadIdx.x;
    int chunk = (n + 1023) >> 10;
    int base = t * chunk;
    int end = base + chunk; if (end > n) end = n;
    int local = 0;
    for (int i = base; i < end; i++) local += g_cnt[i];
    sh[t] = local;
    __syncthreads();
    for (int off = 1; off < 1024; off <<= 1) {
        int add = (t >= off) ? sh[t - off] : 0;
        __syncthreads();
        sh[t] += add;
        __syncthreads();
    }
    int carry = sh[t] - local;   // exclusive prefix of this thread's chunk
    for (int i = base; i < end; i++) {
        int c = g_cnt[i];
        g_rowptr[i] = carry;
        g_fill[i] = carry;                       // fill cursor starts at rowptr[i]
        g_dinv[i] = rsqrtf((float)(c + 1));      // +1 self-loop
        carry += c;
        if (i == n - 1) g_rowptr[n] = carry;
    }
}

__global__ void k_fill(const void* ei, int E) {
    int e = blockIdx.x * blockDim.x + threadIdx.x;
    if (e < E) {
        int s, d; load_edge(ei, E, e, s, d);
        int p = atomicAdd(&g_fill[d], 1);        // cursor = rowptr[d] + seen
        g_col[p] = s;
        g_val[p] = g_dinv[s] * g_dinv[d];
    }
}

// ==================== fused gather + GEMM (layer 1, K=32) ====================
// dyn smem: Xs[32][GR] floats, then Wd[32*128] float2 (duplicated interleaved)
__global__ void __launch_bounds__(256) k_gemm1f(const float* __restrict__ x,
                                                const float* __restrict__ W,
                                                float* __restrict__ Y, int n) {
    extern __shared__ float sm[];
    float (*Xs)[GR] = (float(*)[GR])sm;
    float2* Wd = (float2*)(sm + DIN * GR);
    int tid = threadIdx.x;
    int warp = tid >> 5, lane = tid & 31;
    int r0 = blockIdx.x * 128;

    // stage W as duplicated pairs, interleaved slot = (c&7)*16 + (c>>3)
#pragma unroll
    for (int l = 0; l < 4; l++) {
        int li = tid + l * 256;            // float4 index, 32*32 total
        int k = li >> 5;
        int c4 = (li & 31) * 4;
        float4 v = *(const float4*)(W + (size_t)k * DHD + c4);
        float vv[4] = {v.x, v.y, v.z, v.w};
#pragma unroll
        for (int m = 0; m < 4; m++) {
            int c = c4 + m;
            Wd[k * DHD + (c & 7) * 16 + (c >> 3)] = make_float2(vv[m], vv[m]);
        }
    }

    // gather phase: warp -> 16 nodes, lane = channel, 4-edge unroll for MLP
    for (int i = 0; i < 16; i++) {
        int nl = warp * 16 + i;
        int node = r0 + nl;
        float acc = 0.f;
        if (node < n) {
            float di = g_dinv[node];
            acc = x[(size_t)node * DIN + lane] * di * di;
            int e0 = g_rowptr[node], e1 = g_rowptr[node + 1];
            int e = e0;
            for (; e + 3 < e1; e += 4) {
                int c0 = g_col[e], c1 = g_col[e + 1], c2 = g_col[e + 2], c3 = g_col[e + 3];
                float w0 = g_val[e], w1 = g_val[e + 1], w2 = g_val[e + 2], w3 = g_val[e + 3];
                float v0 = x[(size_t)c0 * DIN + lane];
                float v1 = x[(size_t)c1 * DIN + lane];
                float v2 = x[(size_t)c2 * DIN + lane];
                float v3 = x[(size_t)c3 * DIN + lane];
                acc += v0 * w0 + v1 * w1 + v2 * w2 + v3 * w3;
            }
            for (; e < e1; e++) acc += x[(size_t)g_col[e] * DIN + lane] * g_val[e];
        }
        Xs[lane][nl] = acc;
    }
    __syncthreads();

    int tx = tid & 15, ty = tid >> 4;
    const unsigned long long* Wq = (const unsigned long long*)Wd;
    unsigned long long acc[4][8];
#pragma unroll
    for (int i = 0; i < 4; i++)
#pragma unroll
        for (int j = 0; j < 8; j++) acc[i][j] = 0ULL;

#pragma unroll
    for (int k = 0; k < DIN; k++) {
        unsigned long long ap[4];
#pragma unroll
        for (int i = 0; i < 4; i++)
            ap[i] = *(const unsigned long long*)&Xs[k][ty * 8 + 2 * i];
#pragma unroll
        for (int j = 0; j < 8; j++) {
            unsigned long long bp = Wq[k * DHD + j * 16 + tx];
#pragma unroll
            for (int i = 0; i < 4; i++) FMA2(acc[i][j], ap[i], bp);
        }
    }

    // epilogue: write Y + per-channel stats
    float colsum[8], colsq[8];
#pragma unroll
    for (int j = 0; j < 8; j++) { colsum[j] = 0.f; colsq[j] = 0.f; }
#pragma unroll
    for (int i = 0; i < 4; i++) {
        float lo[8], hi[8];
#pragma unroll
        for (int j = 0; j < 8; j++) {
            unpk2(acc[i][j], lo[j], hi[j]);
            colsum[j] += lo[j] + hi[j];
            colsq[j] += lo[j] * lo[j] + hi[j] * hi[j];
        }
        int gr = r0 + ty * 8 + 2 * i;
        if (gr < n) {
            *(float4*)(Y + (size_t)gr * DHD + tx * 8) = make_float4(lo[0], lo[1], lo[2], lo[3]);
            *(float4*)(Y + (size_t)gr * DHD + tx * 8 + 4) = make_float4(lo[4], lo[5], lo[6], lo[7]);
        }
        if (gr + 1 < n) {
            *(float4*)(Y + (size_t)(gr + 1) * DHD + tx * 8) = make_float4(hi[0], hi[1], hi[2], hi[3]);
            *(float4*)(Y + (size_t)(gr + 1) * DHD + tx * 8 + 4) = make_float4(hi[4], hi[5], hi[6], hi[7]);
        }
    }
    __syncthreads();
    float* red = sm;                       // 16*128 floats
#pragma unroll
    for (int j = 0; j < 8; j++) red[ty * 128 + tx * 8 + j] = colsum[j];
    __syncthreads();
    if (tid < 128) {
        float s = 0.f;
#pragma unroll
        for (int t = 0; t < 16; t++) s += red[t * 128 + tid];
        atomicAdd(&g_sum[tid], (double)s);
    }
    __syncthreads();
#pragma unroll
    for (int j = 0; j < 8; j++) red[ty * 128 + tx * 8 + j] = colsq[j];
    __syncthreads();
    if (tid < 128) {
        float s = 0.f;
#pragma unroll
        for (int t = 0; t < 16; t++) s += red[t * 128 + tid];
        atomicAdd(&g_sq[tid], (double)s);
    }
}

// ============ fused norm-affine + relu + gather + GEMM (layer 2) ============
// dyn smem: Xs[128][GR] floats, then Wd[32*128] float2 (chunked over K)
// Gather: lane owns contiguous channels 4*lane..4*lane+3 -> ONE LDG.128/edge.
__global__ void __launch_bounds__(256) k_gemm2f(const float* __restrict__ h,
                                                const float* __restrict__ W,
                                                float* __restrict__ Y, int n) {
    extern __shared__ float sm[];
    float (*Xs)[GR] = (float(*)[GR])sm;
    float2* Wd = (float2*)(sm + DHD * GR);
    int tid = threadIdx.x;
    int warp = tid >> 5, lane = tid & 31;
    int r0 = blockIdx.x * 128;

    // per-lane norm constants for channels 4*lane..4*lane+3
    float4 sc = ((const float4*)g_scale)[lane];
    float4 bt = ((const float4*)g_beta)[lane];

    // gather phase: warp -> 16 nodes; 4-edge unroll; float4 per edge
    for (int i = 0; i < 16; i++) {
        int nl = warp * 16 + i;
        int node = r0 + nl;
        float a0 = 0.f, a1 = 0.f, a2 = 0.f, a3 = 0.f;
        if (node < n) {
            float di = g_dinv[node];
            float ws = di * di;
            float4 v = ((const float4*)(h + (size_t)node * DHD))[lane];
            a0 = fmaxf(fmaf(v.x, sc.x, bt.x), 0.f) * ws;
            a1 = fmaxf(fmaf(v.y, sc.y, bt.y), 0.f) * ws;
            a2 = fmaxf(fmaf(v.z, sc.z, bt.z), 0.f) * ws;
            a3 = fmaxf(fmaf(v.w, sc.w, bt.w), 0.f) * ws;
            int e0 = g_rowptr[node], e1 = g_rowptr[node + 1];
            int e = e0;
            for (; e + 3 < e1; e += 4) {
                int c0 = g_col[e], c1 = g_col[e + 1], c2 = g_col[e + 2], c3 = g_col[e + 3];
                float w0 = g_val[e], w1 = g_val[e + 1], w2 = g_val[e + 2], w3 = g_val[e + 3];
                float4 u0 = ((const float4*)(h + (size_t)c0 * DHD))[lane];
                float4 u1 = ((const float4*)(h + (size_t)c1 * DHD))[lane];
                float4 u2 = ((const float4*)(h + (size_t)c2 * DHD))[lane];
                float4 u3 = ((const float4*)(h + (size_t)c3 * DHD))[lane];
                a0 += fmaxf(fmaf(u0.x, sc.x, bt.x), 0.f) * w0 + fmaxf(fmaf(u1.x, sc.x, bt.x), 0.f) * w1
                    + fmaxf(fmaf(u2.x, sc.x, bt.x), 0.f) * w2 + fmaxf(fmaf(u3.x, sc.x, bt.x), 0.f) * w3;
                a1 += fmaxf(fmaf(u0.y, sc.y, bt.y), 0.f) * w0 + fmaxf(fmaf(u1.y, sc.y, bt.y), 0.f) * w1
                    + fmaxf(fmaf(u2.y, sc.y, bt.y), 0.f) * w2 + fmaxf(fmaf(u3.y, sc.y, bt.y), 0.f) * w3;
                a2 += fmaxf(fmaf(u0.z, sc.z, bt.z), 0.f) * w0 + fmaxf(fmaf(u1.z, sc.z, bt.z), 0.f) * w1
                    + fmaxf(fmaf(u2.z, sc.z, bt.z), 0.f) * w2 + fmaxf(fmaf(u3.z, sc.z, bt.z), 0.f) * w3;
                a3 += fmaxf(fmaf(u0.w, sc.w, bt.w), 0.f) * w0 + fmaxf(fmaf(u1.w, sc.w, bt.w), 0.f) * w1
                    + fmaxf(fmaf(u2.w, sc.w, bt.w), 0.f) * w2 + fmaxf(fmaf(u3.w, sc.w, bt.w), 0.f) * w3;
            }
            for (; e < e1; e++) {
                int c0 = g_col[e]; float w0 = g_val[e];
                float4 u0 = ((const float4*)(h + (size_t)c0 * DHD))[lane];
                a0 += fmaxf(fmaf(u0.x, sc.x, bt.x), 0.f) * w0;
                a1 += fmaxf(fmaf(u0.y, sc.y, bt.y), 0.f) * w0;
                a2 += fmaxf(fmaf(u0.z, sc.z, bt.z), 0.f) * w0;
                a3 += fmaxf(fmaf(u0.w, sc.w, bt.w), 0.f) * w0;
            }
        }
        Xs[4 * lane + 0][nl] = a0;
        Xs[4 * lane + 1][nl] = a1;
        Xs[4 * lane + 2][nl] = a2;
        Xs[4 * lane + 3][nl] = a3;
    }

    int tx = tid & 15, ty = tid >> 4;
    const unsigned long long* Wq = (const unsigned long long*)Wd;
    unsigned long long acc[4][8];
#pragma unroll
    for (int i = 0; i < 4; i++)
#pragma unroll
        for (int j = 0; j < 8; j++) acc[i][j] = 0ULL;

    for (int kc = 0; kc < DHD; kc += 32) {
        __syncthreads();   // gather done (first iter) / previous chunk consumed
#pragma unroll
        for (int l = 0; l < 4; l++) {
            int li = tid + l * 256;
            int k = li >> 5;
            int c4 = (li & 31) * 4;
            float4 v = *(const float4*)(W + (size_t)(kc + k) * DHD + c4);
            float vv[4] = {v.x, v.y, v.z, v.w};
#pragma unroll
            for (int m = 0; m < 4; m++) {
                int c = c4 + m;
                Wd[k * DHD + (c & 7) * 16 + (c >> 3)] = make_float2(vv[m], vv[m]);
            }
        }
        __syncthreads();
#pragma unroll
        for (int k = 0; k < 32; k++) {
            unsigned long long ap[4];
#pragma unroll
            for (int i = 0; i < 4; i++)
                ap[i] = *(const unsigned long long*)&Xs[kc + k][ty * 8 + 2 * i];
#pragma unroll
            for (int j = 0; j < 8; j++) {
                unsigned long long bp = Wq[k * DHD + j * 16 + tx];
#pragma unroll
                for (int i = 0; i < 4; i++) FMA2(acc[i][j], ap[i], bp);
            }
        }
    }

    // epilogue: write Y + per-channel stats
    float colsum[8], colsq[8];
#pragma unroll
    for (int j = 0; j < 8; j++) { colsum[j] = 0.f; colsq[j] = 0.f; }
#pragma unroll
    for (int i = 0; i < 4; i++) {
        float lo[8], hi[8];
#pragma unroll
        for (int j = 0; j < 8; j++) {
            unpk2(acc[i][j], lo[j], hi[j]);
            colsum[j] += lo[j] + hi[j];
            colsq[j] += lo[j] * lo[j] + hi[j] * hi[j];
        }
        int gr = r0 + ty * 8 + 2 * i;
        if (gr < n) {
            *(float4*)(Y + (size_t)gr * DHD + tx * 8) = make_float4(lo[0], lo[1], lo[2], lo[3]);
            *(float4*)(Y + (size_t)gr * DHD + tx * 8 + 4) = make_float4(lo[4], lo[5], lo[6], lo[7]);
        }
        if (gr + 1 < n) {
            *(float4*)(Y + (size_t)(gr + 1) * DHD + tx * 8) = make_float4(hi[0], hi[1], hi[2], hi[3]);
            *(float4*)(Y + (size_t)(gr + 1) * DHD + tx * 8 + 4) = make_float4(hi[4], hi[5], hi[6], hi[7]);
        }
    }
    __syncthreads();
    float* red = sm;
#pragma unroll
    for (int j = 0; j < 8; j++) red[ty * 128 + tx * 8 + j] = colsum[j];
    __syncthreads();
    if (tid < 128) {
        float s = 0.f;
#pragma unroll
        for (int t = 0; t < 16; t++) s += red[t * 128 + tid];
        atomicAdd(&g_sum[tid], (double)s);
    }
    __syncthreads();
#pragma unroll
    for (int j = 0; j < 8; j++) red[ty * 128 + tx * 8 + j] = colsq[j];
    __syncthreads();
    if (tid < 128) {
        float s = 0.f;
#pragma unroll
        for (int t = 0; t < 16; t++) s += red[t * 128 + tid];
        atomicAdd(&g_sq[tid], (double)s);
    }
}

// ---- GEMV with fused affine+relu on input: y = relu(H*s+b) @ w3 -----------
__global__ void __launch_bounds__(256) k_gemv(const float* __restrict__ H,
                                              const float* __restrict__ W3,
                                              float* __restrict__ y, int n) {
    __shared__ float w[DHD], sc[DHD], bt[DHD];
    if (threadIdx.x < DHD) {
        w[threadIdx.x] = W3[threadIdx.x];
        sc[threadIdx.x] = g_scale[threadIdx.x];
        bt[threadIdx.x] = g_beta[threadIdx.x];
    }
    __syncthreads();
    int warp = threadIdx.x >> 5, lane = threadIdx.x & 31;
    int row = blockIdx.x * 8 + warp;
    if (row >= n) return;
    const float* h = H + (size_t)row * DHD;
    float s = 0.f;
#pragma unroll
    for (int k = 0; k < 4; k++) {
        int c = lane + 32 * k;
        float v = fmaxf(fmaf(h[c], sc[c], bt[c]), 0.f);
        s = fmaf(v, w[c], s);
    }
#pragma unroll
    for (int o = 16; o; o >>= 1) s += __shfl_xor_sync(0xFFFFFFFFu, s, o);
    if (lane == 0) y[row] = s;
}

// ---- layer-3 scalar gather with fused stats (block-reduce + atomic) --------
__global__ void k_gather1s(const float* __restrict__ y, float* __restrict__ out, int n) {
    __shared__ float s1[256], s2[256];
    int t = threadIdx.x;
    int i = blockIdx.x * blockDim.x + t;
    float acc = 0.f;
    if (i < n) {
        float di = g_dinv[i];
        acc = y[i] * di * di;
        int e0 = g_rowptr[i], e1 = g_rowptr[i + 1];
        int e = e0;
        for (; e + 3 < e1; e += 4) {
            int c0 = g_col[e], c1 = g_col[e + 1], c2 = g_col[e + 2], c3 = g_col[e + 3];
            float y0 = y[c0], y1 = y[c1], y2 = y[c2], y3 = y[c3];
            acc += y0 * g_val[e] + y1 * g_val[e + 1] + y2 * g_val[e + 2] + y3 * g_val[e + 3];
        }
        for (; e < e1; e++) acc += y[g_col[e]] * g_val[e];
        out[i] = acc;
    }
    s1[t] = (i < n) ? acc : 0.f;
    s2[t] = (i < n) ? acc * acc : 0.f;
    __syncthreads();
    for (int o = 128; o; o >>= 1) {
        if (t < o) { s1[t] += s1[t + o]; s2[t] += s2[t + o]; }
        __syncthreads();
    }
    if (t == 0) {
        atomicAdd(&g_sum[0], (double)s1[0]);
        atomicAdd(&g_sq[0], (double)s2[0]);
    }
}

// bn∘inorm∘lnorm collapses to v*scale_c + beta_c (lnorm global mean is 0).
// Also resets g_sum/g_sq for the next layer's accumulation.
__global__ void k_consts(const float* __restrict__ g, const float* __restrict__ lw,
                         const float* __restrict__ lb, int C, int n) {
    __shared__ float red[128];
    int c = threadIdx.x;
    float alpha = 0.f, v = 0.f, m = 0.f;
    if (c < C) {
        double md = g_sum[c] / (double)n;
        double vd = g_sq[c] / (double)n - md * md;
        if (vd < 0.0) vd = 0.0;
        m = (float)md; v = (float)vd;
        float r1 = rsqrtf(v + EPSC);
        float gv = g[c];
        float var1 = gv * gv * v * r1 * r1;       // var of BN output
        alpha = gv * r1 * rsqrtf(var1 + EPSC);    // inorm(bn(.)) slope
        red[c] = alpha * alpha * v;               // contribution to lnorm var
    } else {
        red[c] = 0.f;
    }
    __syncthreads();
    for (int o = 64; o; o >>= 1) {
        if (c < o) red[c] += red[c + o];
        __syncthreads();
    }
    float v2 = red[0] / (float)C;
    if (c < C) {
        float s = alpha * rsqrtf(v2 + EPSC) * lw[c];
        g_scale[c] = s;
        g_beta[c] = lb[c] - m * s;
    }
    // reset stats for next layer (own slot only; read already done above)
    g_sum[c] = 0.0;
    g_sq[c] = 0.0;
}

__global__ void k_final(const float* __restrict__ gy, float* __restrict__ out, int n) {
    int i = blockIdx.x * blockDim.x + threadIdx.x;
    if (i < n) out[i] = fmaf(gy[i], g_scale[0], g_beta[0]);
}

// ------------------------------ launch --------------------------------------
extern "C" void kernel_launch(void* const* d_in, const int* in_sizes, int n_in,
                              void* d_out, int out_size) {
    const float* x  = (const float*)d_in[0];
    const void*  ei = d_in[1];
    const float* W1 = (const float*)d_in[2];
    const float* g1 = (const float*)d_in[4];
    const float* lw1 = (const float*)d_in[6];
    const float* lb1 = (const float*)d_in[7];
    const float* W2 = (const float*)d_in[8];
    const float* g2 = (const float*)d_in[10];
    const float* lw2 = (const float*)d_in[12];
    const float* lb2 = (const float*)d_in[13];
    const float* W3 = (const float*)d_in[14];
    const float* g3 = (const float*)d_in[16];
    const float* lw3 = (const float*)d_in[18];
    const float* lb3 = (const float*)d_in[19];

    int n = in_sizes[0] / DIN;   // 100000
    int E = in_sizes[1] / 2;     // 400000

    const int SM1 = DIN * GR * 4 + DIN * DHD * 8;   // 16640 + 32768 = 49408
    const int SM2 = DHD * GR * 4 + 32 * DHD * 8;    // 66560 + 32768 = 99328
    cudaFuncSetAttribute(k_gemm1f, cudaFuncAttributeMaxDynamicSharedMemorySize, SM1);
    cudaFuncSetAttribute(k_gemm2f, cudaFuncAttributeMaxDynamicSharedMemorySize, SM2);

    float* Hb; float* Ab; float* yb; float* gyb;
    cudaGetSymbolAddress((void**)&Hb,  g_H);
    cudaGetSymbolAddress((void**)&Ab,  g_A);
    cudaGetSymbolAddress((void**)&yb,  g_y);
    cudaGetSymbolAddress((void**)&gyb, g_gy);

    int nblk = (n + 127) / 128;

    // ---- graph preprocessing (4 kernels) ----
    k_zero_init<<<(n + 255) / 256, 256>>>(ei, n);
    k_count<<<(E + 255) / 256, 256>>>(ei, E);
    k_scan_one<<<1, 1024>>>(n);                    // rowptr + fill cursor + dinv
    k_fill<<<(E + 255) / 256, 256>>>(ei, E);

    // ---- layer 1: fused gather(x) + GEMM1 (+stats), consts (+stats reset) ----
    k_gemm1f<<<nblk, 256, SM1>>>(x, W1, Hb, n);
    k_consts<<<1, 128>>>(g1, lw1, lb1, DHD, n);

    // ---- layer 2: fused norm+relu+gather(h1) + GEMM2 (+stats), consts ----
    k_gemm2f<<<nblk, 256, SM2>>>(Hb, W2, Ab, n);
    k_consts<<<1, 128>>>(g2, lw2, lb2, DHD, n);

    // ---- layer 3: (norm(h2) @ W3) then scalar aggregation (+stats fused) ----
    k_gemv<<<(n + 7) / 8, 256>>>(Ab, W3, yb, n);
    k_gather1s<<<(n + 255) / 256, 256>>>(yb, gyb, n);
    k_consts<<<1, 128>>>(g3, lw3, lb3, 1, n);
    k_final<<<(n + 255) / 256, 256>>>(gyb, (float*)d_out, n);
}